// round 5
// baseline (speedup 1.0000x reference)
#include <cuda_runtime.h>
#include <cuda_bf16.h>
#include <cstdint>
#include <math.h>

#define BATCH 8192
#define DIM   256
#define BM    128
#define BN    64
#define COLSPER 2048
#define TILES (COLSPER / BN)      // 32
#define THREADS 256
#define NCH    4

#define SCALE_L2 1442.6950408889634f   // 1000 * log2(e)
#define LN2F     0.69314718055994531f
#define MAGICF   12582912.0f           // 2^23 + 2^22
#define MAGICI   0x4B400000

// ---- shared memory layout (dynamic) ----
#define SA     0                        // A tile 128x256 int8 (32KB, swizzled)
#define SB0    32768                    // B tile buf0 (16KB)
#define SB1    49152                    // B tile buf1 (16KB)
#define SMRG_M 65536                    // 128*4 floats (2KB)
#define SMRG_S 67584                    // 128*4 floats (2KB)
#define SMEM_BYTES 69632

// ---- device globals (no allocation allowed) ----
__device__ uint32_t g_zi8[BATCH * DIM / 4];   // packed int8
__device__ uint32_t g_zj8[BATCH * DIM / 4];
__device__ float g_n1[BATCH];
__device__ float g_n2[BATCH];
__device__ float g_diag[BATCH];
__device__ float g_pm[NCH][BATCH];
__device__ float g_ps[NCH][BATCH];
__device__ unsigned int g_absmax_bits;
__device__ float g_loss_sum;
__device__ float g_diag_sum;
__device__ unsigned int g_done;

// ================= PTX helpers =================
__device__ __forceinline__ uint32_t smem_u32(const void* p) {
    uint32_t a;
    asm("{ .reg .u64 t; cvta.to.shared.u64 t, %1; cvt.u32.u64 %0, t; }" : "=r"(a) : "l"(p));
    return a;
}
__device__ __forceinline__ float ex2f(float x) {
    float r; asm("ex2.approx.f32 %0, %1;" : "=f"(r) : "f"(x)); return r;
}
__device__ __forceinline__ void cp16(uint32_t dst, const void* src) {
    asm volatile("cp.async.cg.shared.global [%0], [%1], 16;" :: "r"(dst), "l"(src) : "memory");
}
__device__ __forceinline__ void cp_commit() { asm volatile("cp.async.commit_group;" ::: "memory"); }
template <int N> __device__ __forceinline__ void cp_wait() {
    asm volatile("cp.async.wait_group %0;" :: "n"(N) : "memory");
}
__device__ __forceinline__ void ldsm_x4(uint32_t* r, uint32_t addr) {
    asm volatile("ldmatrix.sync.aligned.m8n8.x4.shared.b16 {%0,%1,%2,%3}, [%4];\n"
                 : "=r"(r[0]), "=r"(r[1]), "=r"(r[2]), "=r"(r[3])
                 : "r"(addr));
}
__device__ __forceinline__ void mma_s8(int* d, const uint32_t* a, const uint32_t* b) {
    asm volatile(
        "mma.sync.aligned.m16n8k32.row.col.s32.s8.s8.s32 "
        "{%0,%1,%2,%3}, {%4,%5,%6,%7}, {%8,%9}, {%0,%1,%2,%3};\n"
        : "+r"(d[0]), "+r"(d[1]), "+r"(d[2]), "+r"(d[3])
        : "r"(a[0]), "r"(a[1]), "r"(a[2]), "r"(a[3]), "r"(b[0]), "r"(b[1]));
}

// swizzled chunk position inside a 256B row: chunk c in 0..15
__device__ __forceinline__ uint32_t chunk_pos(int r, int c) {
    return (uint32_t)(((c & 8) | ((c ^ r) & 7)) << 4);
}

// load a 128x256 int8 tile (32KB) into swizzled smem via cp.async
__device__ __forceinline__ void load_tile_a(uint32_t dst, const uint32_t* src, int tid) {
    const char* s = (const char*)src;
    #pragma unroll
    for (int i = 0; i < 8; i++) {
        int idx = tid + i * THREADS;       // 0..2047
        int r = idx >> 4;                  // row 0..127
        int c = idx & 15;
        cp16(dst + r * 256 + chunk_pos(r, c), s + (size_t)r * 256 + (size_t)c * 16);
    }
}
// load a 64x256 int8 tile (16KB)
__device__ __forceinline__ void load_tile_b(uint32_t dst, const uint32_t* src, int tid) {
    const char* s = (const char*)src;
    #pragma unroll
    for (int i = 0; i < 4; i++) {
        int idx = tid + i * THREADS;       // 0..1023
        int r = idx >> 4;                  // row 0..63
        int c = idx & 15;
        cp16(dst + r * 256 + chunk_pos(r, c), s + (size_t)r * 256 + (size_t)c * 16);
    }
}

// ================= kernels =================
__global__ void cl_init_kernel() {
    g_diag_sum = 0.0f;
    g_loss_sum = 0.0f;
    g_absmax_bits = 0u;
    g_done = 0u;
}

// pass 1: row norms, exact fp32 diagonal, global max |z| (post-normalize)
__global__ void cl_prep_kernel(const float* __restrict__ p1,
                               const float* __restrict__ p2) {
    int row = blockIdx.x;
    int t = threadIdx.x;

    float v1 = p1[row * DIM + t];
    float v2 = p2[row * DIM + t];

    float s1 = v1 * v1, s2 = v2 * v2, s3 = v1 * v2;
    #pragma unroll
    for (int o = 16; o > 0; o >>= 1) {
        s1 += __shfl_down_sync(0xffffffffu, s1, o);
        s2 += __shfl_down_sync(0xffffffffu, s2, o);
        s3 += __shfl_down_sync(0xffffffffu, s3, o);
    }
    __shared__ float sh1[8], sh2[8], sh3[8], shm[8];
    __shared__ float rn1, rn2;
    int wid = t >> 5;
    if ((t & 31) == 0) { sh1[wid] = s1; sh2[wid] = s2; sh3[wid] = s3; }
    __syncthreads();
    if (t == 0) {
        float a = 0.f, b = 0.f, c = 0.f;
        #pragma unroll
        for (int i = 0; i < 8; i++) { a += sh1[i]; b += sh2[i]; c += sh3[i]; }
        float n1 = fmaxf(sqrtf(a), 1e-12f);
        float n2 = fmaxf(sqrtf(b), 1e-12f);
        rn1 = n1; rn2 = n2;
        g_n1[row] = n1;
        g_n2[row] = n2;
        g_diag[row] = c / (n1 * n2);
    }
    __syncthreads();
    float mx = fmaxf(fabsf(v1) / rn1, fabsf(v2) / rn2);
    #pragma unroll
    for (int o = 16; o > 0; o >>= 1)
        mx = fmaxf(mx, __shfl_down_sync(0xffffffffu, mx, o));
    if ((t & 31) == 0) shm[wid] = mx;
    __syncthreads();
    if (t == 0) {
        float m = shm[0];
        #pragma unroll
        for (int i = 1; i < 8; i++) m = fmaxf(m, shm[i]);
        atomicMax(&g_absmax_bits, __float_as_uint(m));   // positive floats: bit-monotone
    }
}

// pass 2: quantize both tensors to int8 with the exact global scale
__global__ void cl_quant_kernel(const float* __restrict__ p1,
                                const float* __restrict__ p2) {
    int g = blockIdx.x * 256 + threadIdx.x;
    int row = g >> 6;
    float S = __uint_as_float(g_absmax_bits);
    float q = 127.0f / S;
    float q1 = q / g_n1[row];
    float q2 = q / g_n2[row];

    float4 a = ((const float4*)p1)[g];
    float4 b = ((const float4*)p2)[g];

    int a0 = __float2int_rn(a.x * q1), a1 = __float2int_rn(a.y * q1);
    int a2 = __float2int_rn(a.z * q1), a3 = __float2int_rn(a.w * q1);
    int b0 = __float2int_rn(b.x * q2), b1 = __float2int_rn(b.y * q2);
    int b2 = __float2int_rn(b.z * q2), b3 = __float2int_rn(b.w * q2);

    g_zi8[g] = (a0 & 0xff) | ((a1 & 0xff) << 8) | ((a2 & 0xff) << 16) | (a3 << 24);
    g_zj8[g] = (b0 & 0xff) | ((b1 & 0xff) << 8) | ((b2 & 0xff) << 16) | (b3 << 24);
}

// fused int8 IMMA GEMM + online LSE.
// grid = 256 (64 row-blocks x 4 col-quarters), 2 CTAs/SM -> MMA/epilogue overlap
// 8 warps as 2x4 over the 128x64 tile -> warp tile 64x16
__global__ void __launch_bounds__(THREADS, 2)
cl_main_kernel() {
    extern __shared__ char smem[];
    uint32_t sb = smem_u32(smem);
    const int tid  = threadIdx.x;
    const int warp = tid >> 5;
    const int lane = tid & 31;
    const int warp_m = warp >> 2;       // 0..1 : 64 rows
    const int warp_n = warp & 3;        // 0..3 : 16 cols
    const int rb   = (blockIdx.x >> 2) * BM;
    const int ch   = blockIdx.x & 3;
    const int col0 = ch * COLSPER;

    const float S = __uint_as_float(g_absmax_bits);
    const float kk = SCALE_L2 * (S * S) * (1.0f / 16129.0f);

    // prologue
    load_tile_a(sb + SA,  g_zi8 + (size_t)rb * (DIM / 4), tid);
    load_tile_b(sb + SB0, g_zj8 + (size_t)col0 * (DIM / 4), tid);
    cp_commit();
    load_tile_b(sb + SB1, g_zj8 + (size_t)(col0 + BN) * (DIM / 4), tid);
    cp_commit();
    cp_wait<1>();
    __syncthreads();

    float m_run[8], s_run[8];
    #pragma unroll
    for (int i = 0; i < 8; i++) { m_run[i] = -1.0e9f; s_run[i] = 0.0f; }

    const int mrow = lane & 7;
    const int am = lane >> 3;

    for (int t = 0; t < TILES; ++t) {
        const int sel = t & 1;
        const uint32_t bbase = sb + (sel ? SB1 : SB0);

        int acc[4][2][4];
        #pragma unroll
        for (int mi = 0; mi < 4; mi++)
            #pragma unroll
            for (int ni = 0; ni < 2; ni++)
                #pragma unroll
                for (int q = 0; q < 4; q++)
                    acc[mi][ni][q] = 0;

        #pragma unroll
        for (int ks = 0; ks < 8; ks++) {
            uint32_t a[4][4];
            {
                int achk = 2 * ks + (am >> 1);
                #pragma unroll
                for (int mi = 0; mi < 4; mi++) {
                    int row = warp_m * 64 + mi * 16 + ((am & 1) << 3) + mrow;
                    ldsm_x4(a[mi], sb + SA + row * 256 + chunk_pos(row, achk));
                }
            }
            uint32_t b[2][2];
            {
                int bchk = 2 * ks + (am & 1);
                int col = warp_n * 16 + ((am >> 1) << 3) + mrow;
                uint32_t r4[4];
                ldsm_x4(r4, bbase + col * 256 + chunk_pos(col, bchk));
                b[0][0] = r4[0]; b[0][1] = r4[1];
                b[1][0] = r4[2]; b[1][1] = r4[3];
            }
            #pragma unroll
            for (int mi = 0; mi < 4; mi++)
                #pragma unroll
                for (int ni = 0; ni < 2; ni++)
                    mma_s8(acc[mi][ni], a[mi], b[ni]);
        }

        __syncthreads();   // all warps done reading Bs[sel]

        if (t + 2 < TILES) {
            load_tile_b(bbase, g_zj8 + (size_t)(col0 + (t + 2) * BN) * (DIM / 4), tid);
            cp_commit();
        }

        // ---- epilogue: online LSE update, 8 row-slots x 4 cols of int32 ----
        #pragma unroll
        for (int mi = 0; mi < 4; mi++) {
            #pragma unroll
            for (int h = 0; h < 2; h++) {
                int idx = mi * 2 + h;
                int y[4];
                y[0] = acc[mi][0][h * 2];
                y[1] = acc[mi][0][h * 2 + 1];
                y[2] = acc[mi][1][h * 2];
                y[3] = acc[mi][1][h * 2 + 1];
                int tmi = max(max(y[0], y[1]), max(y[2], y[3]));
                float nm = fmaxf(m_run[idx], (float)tmi);
                float nb = -(nm + MAGICF) * kk;       // folds int->float magic bias
                float a0 = 0.f;
                #pragma unroll
                for (int j = 0; j < 4; j++)
                    a0 += ex2f(fmaf(__int_as_float(y[j] + MAGICI), kk, nb));
                s_run[idx] = s_run[idx] * ex2f((m_run[idx] - nm) * kk) + a0;
                m_run[idx] = nm;
            }
        }

        if (t + 2 < TILES) cp_wait<1>(); else cp_wait<0>();
        __syncthreads();
    }

    // ---- reduce across lanes sharing a row (lane&3 varies) ----
    #pragma unroll
    for (int idx = 0; idx < 8; idx++) {
        #pragma unroll
        for (int o = 1; o <= 2; o <<= 1) {
            float om = __shfl_xor_sync(0xffffffffu, m_run[idx], o);
            float os = __shfl_xor_sync(0xffffffffu, s_run[idx], o);
            float nm = fmaxf(m_run[idx], om);
            s_run[idx] = s_run[idx] * ex2f((m_run[idx] - nm) * kk)
                       + os         * ex2f((om         - nm) * kk);
            m_run[idx] = nm;
        }
    }

    // ---- merge across the 4 column-warps via smem ----
    float* mrg_m = (float*)(smem + SMRG_M);
    float* mrg_s = (float*)(smem + SMRG_S);
    if ((lane & 3) == 0) {
        #pragma unroll
        for (int idx = 0; idx < 8; idx++) {
            int row = warp_m * 64 + (idx >> 1) * 16 + (idx & 1) * 8 + (lane >> 2);
            mrg_m[row * 4 + warp_n] = m_run[idx];
            mrg_s[row * 4 + warp_n] = s_run[idx];
        }
    }
    __syncthreads();

    if (tid < BM) {
        int row = tid;
        float m = mrg_m[row * 4];
        #pragma unroll
        for (int w = 1; w < 4; w++) m = fmaxf(m, mrg_m[row * 4 + w]);
        float s = 0.0f;
        #pragma unroll
        for (int w = 0; w < 4; w++)
            s += mrg_s[row * 4 + w] * ex2f((mrg_m[row * 4 + w] - m) * kk);
        g_pm[ch][rb + row] = m;
        g_ps[ch][rb + row] = s;
    }
}

// merge the 4 column-quarter partials per row, reduce loss + diag, last block writes out
__global__ void cl_merge_kernel(float* out, int out_size) {
    int r = blockIdx.x * 256 + threadIdx.x;
    float S = __uint_as_float(g_absmax_bits);
    float kk = SCALE_L2 * (S * S) * (1.0f / 16129.0f);

    float m = g_pm[0][r];
    #pragma unroll
    for (int c = 1; c < NCH; c++) m = fmaxf(m, g_pm[c][r]);
    float s = 0.0f;
    #pragma unroll
    for (int c = 0; c < NCH; c++)
        s += g_ps[c][r] * ex2f((g_pm[c][r] - m) * kk);

    float d = g_diag[r];
    float loss = LN2F * fmaf(m, kk, log2f(s)) - 1000.0f * d;
    float ds = d;
    #pragma unroll
    for (int o = 16; o; o >>= 1) {
        loss += __shfl_down_sync(0xffffffffu, loss, o);
        ds   += __shfl_down_sync(0xffffffffu, ds, o);
    }
    __shared__ float sl[8], sd[8];
    if ((threadIdx.x & 31) == 0) { sl[threadIdx.x >> 5] = loss; sd[threadIdx.x >> 5] = ds; }
    __syncthreads();
    if (threadIdx.x == 0) {
        float L = 0.f, D = 0.f;
        #pragma unroll
        for (int i = 0; i < 8; i++) { L += sl[i]; D += sd[i]; }
        atomicAdd(&g_loss_sum, L);
        atomicAdd(&g_diag_sum, D);
        __threadfence();
        unsigned int ticket = atomicAdd(&g_done, 1u);
        if (ticket == gridDim.x - 1) {      // last block: sums complete
            if (out_size > 0) out[0] = *(volatile float*)&g_loss_sum / (float)BATCH;
            if (out_size > 1) out[1] = *(volatile float*)&g_diag_sum;
        }
    }
}

// ================= launch =================
extern "C" void kernel_launch(void* const* d_in, const int* in_sizes, int n_in,
                              void* d_out, int out_size) {
    const float* p1 = (const float*)d_in[0];
    const float* p2 = (const float*)d_in[1];
    float* out = (float*)d_out;

    cudaFuncSetAttribute(cl_main_kernel,
                         cudaFuncAttributeMaxDynamicSharedMemorySize, SMEM_BYTES);

    cl_init_kernel<<<1, 1>>>();
    cl_prep_kernel<<<BATCH, DIM>>>(p1, p2);
    cl_quant_kernel<<<BATCH * DIM / 4 / 256, 256>>>(p1, p2);
    cl_main_kernel<<<BATCH / BM * NCH, THREADS, SMEM_BYTES>>>();
    cl_merge_kernel<<<BATCH / 256, 256>>>(out, out_size);
}

// round 6
// speedup vs baseline: 1.0406x; 1.0406x over previous
#include <cuda_runtime.h>
#include <cuda_bf16.h>
#include <cstdint>
#include <math.h>

#define BATCH 8192
#define DIM   256
#define BM    128
#define BN    128
#define COLSPER 4096
#define TILES (COLSPER / BN)      // 32
#define THREADS 512
#define NCH    2

#define SCALE_L2 1442.6950408889634f   // 1000 * log2(e)
#define LN2F     0.69314718055994531f
#define MAGICF   12582912.0f           // 2^23 + 2^22
#define MAGICI   0x4B400000

// ---- shared memory layout (dynamic) ----
#define SA     0                        // A tile 128x256 int8 (32KB, swizzled)
#define SB0    32768                    // B tile buf0 (32KB)
#define SB1    65536                    // B tile buf1 (32KB)
#define SMRG_M 98304                    // 128*4 floats (2KB)
#define SMRG_S 100352                   // 128*4 floats (2KB)
#define SMEM_BYTES 102400

// ---- device globals (no allocation allowed) ----
__device__ uint32_t g_zi8[BATCH * DIM / 4];   // packed int8
__device__ uint32_t g_zj8[BATCH * DIM / 4];
__device__ float g_n1[BATCH];
__device__ float g_n2[BATCH];
__device__ float g_diag[BATCH];
__device__ float g_pm[NCH][BATCH];
__device__ float g_ps[NCH][BATCH];
__device__ unsigned int g_absmax_bits;
__device__ float g_loss_sum;
__device__ float g_diag_sum;
__device__ unsigned int g_done;

// ================= PTX helpers =================
__device__ __forceinline__ uint32_t smem_u32(const void* p) {
    uint32_t a;
    asm("{ .reg .u64 t; cvta.to.shared.u64 t, %1; cvt.u32.u64 %0, t; }" : "=r"(a) : "l"(p));
    return a;
}
__device__ __forceinline__ float ex2f(float x) {
    float r; asm("ex2.approx.f32 %0, %1;" : "=f"(r) : "f"(x)); return r;
}
__device__ __forceinline__ void cp16(uint32_t dst, const void* src) {
    asm volatile("cp.async.cg.shared.global [%0], [%1], 16;" :: "r"(dst), "l"(src) : "memory");
}
__device__ __forceinline__ void cp_commit() { asm volatile("cp.async.commit_group;" ::: "memory"); }
template <int N> __device__ __forceinline__ void cp_wait() {
    asm volatile("cp.async.wait_group %0;" :: "n"(N) : "memory");
}
__device__ __forceinline__ void ldsm_x4(uint32_t* r, uint32_t addr) {
    asm volatile("ldmatrix.sync.aligned.m8n8.x4.shared.b16 {%0,%1,%2,%3}, [%4];\n"
                 : "=r"(r[0]), "=r"(r[1]), "=r"(r[2]), "=r"(r[3])
                 : "r"(addr));
}
__device__ __forceinline__ void mma_s8(int* d, const uint32_t* a, const uint32_t* b) {
    asm volatile(
        "mma.sync.aligned.m16n8k32.row.col.s32.s8.s8.s32 "
        "{%0,%1,%2,%3}, {%4,%5,%6,%7}, {%8,%9}, {%0,%1,%2,%3};\n"
        : "+r"(d[0]), "+r"(d[1]), "+r"(d[2]), "+r"(d[3])
        : "r"(a[0]), "r"(a[1]), "r"(a[2]), "r"(a[3]), "r"(b[0]), "r"(b[1]));
}

// swizzled chunk position inside a 256B row: chunk c in 0..15
__device__ __forceinline__ uint32_t chunk_pos(int r, int c) {
    return (uint32_t)(((c & 8) | ((c ^ r) & 7)) << 4);
}

// load a 128x256 int8 tile (32KB) into swizzled smem via cp.async (512 threads)
__device__ __forceinline__ void load_tile(uint32_t dst, const uint32_t* src, int tid) {
    const char* s = (const char*)src;
    #pragma unroll
    for (int i = 0; i < 4; i++) {
        int idx = tid + i * THREADS;       // 0..2047
        int r = idx >> 4;                  // row 0..127
        int c = idx & 15;
        cp16(dst + r * 256 + chunk_pos(r, c), s + (size_t)r * 256 + (size_t)c * 16);
    }
}

// one online-LSE slot update: 8 int32 values -> (m_run, s_run)[slot]
__device__ __forceinline__ void epi_slot(const int acc[2][4][4], int slot,
                                         float* m_run, float* s_run, float kk) {
    const int mi = slot >> 1, h = slot & 1;
    int y[8];
    #pragma unroll
    for (int ni = 0; ni < 4; ni++) {
        y[ni * 2]     = acc[mi][ni][h * 2];
        y[ni * 2 + 1] = acc[mi][ni][h * 2 + 1];
    }
    int t0 = max(y[0], y[1]), t1 = max(y[2], y[3]);
    int t2 = max(y[4], y[5]), t3 = max(y[6], y[7]);
    int tmi = max(max(t0, t1), max(t2, t3));
    float nm = fmaxf(m_run[slot], (float)tmi);
    float nb = -(nm + MAGICF) * kk;           // folds int->float magic bias
    float a0 = 0.f, a1 = 0.f;
    #pragma unroll
    for (int j = 0; j < 4; j++) {
        a0 += ex2f(fmaf(__int_as_float(y[2 * j] + MAGICI), kk, nb));
        a1 += ex2f(fmaf(__int_as_float(y[2 * j + 1] + MAGICI), kk, nb));
    }
    s_run[slot] = s_run[slot] * ex2f((m_run[slot] - nm) * kk) + (a0 + a1);
    m_run[slot] = nm;
}

// MMA one 128x128x256 tile into accc; interleave epilogue of accp (if EPI)
template <bool EPI>
__device__ __forceinline__ void do_tile(uint32_t sb, uint32_t bbase,
                                        int warp_m, int warp_n, int lane,
                                        int accc[2][4][4], const int accp[2][4][4],
                                        float* m_run, float* s_run, float kk) {
    const int mrow = lane & 7;
    const int am = lane >> 3;
    #pragma unroll
    for (int mi = 0; mi < 2; mi++)
        #pragma unroll
        for (int ni = 0; ni < 4; ni++)
            #pragma unroll
            for (int q = 0; q < 4; q++)
                accc[mi][ni][q] = 0;

    #pragma unroll
    for (int ks = 0; ks < 8; ks++) {
        uint32_t a[2][4];
        {
            int achk = 2 * ks + (am >> 1);
            #pragma unroll
            for (int mi = 0; mi < 2; mi++) {
                int row = warp_m * 32 + mi * 16 + ((am & 1) << 3) + mrow;
                ldsm_x4(a[mi], sb + SA + row * 256 + chunk_pos(row, achk));
            }
        }
        uint32_t b[4][2];
        {
            int bchk = 2 * ks + (am & 1);
            #pragma unroll
            for (int np = 0; np < 2; np++) {
                int col = warp_n * 32 + np * 16 + ((am >> 1) << 3) + mrow;
                uint32_t r4[4];
                ldsm_x4(r4, bbase + col * 256 + chunk_pos(col, bchk));
                b[np * 2][0] = r4[0];     b[np * 2][1] = r4[1];
                b[np * 2 + 1][0] = r4[2]; b[np * 2 + 1][1] = r4[3];
            }
        }
        #pragma unroll
        for (int mi = 0; mi < 2; mi++)
            #pragma unroll
            for (int ni = 0; ni < 4; ni++)
                mma_s8(accc[mi][ni], a[mi], b[ni]);

        // interleave one epilogue slot of the PREVIOUS tile after odd k-steps:
        // reads only accp registers -> fills the tensor pipe's shadow
        if (EPI && (ks & 1)) epi_slot(accp, (ks - 1) >> 1, m_run, s_run, kk);
    }
}

// ================= kernels =================
__global__ void cl_init_kernel() {
    g_diag_sum = 0.0f;
    g_loss_sum = 0.0f;
    g_absmax_bits = 0u;
    g_done = 0u;
}

// pass 1: row norms, exact fp32 diagonal, global max |z| (post-normalize)
__global__ void cl_prep_kernel(const float* __restrict__ p1,
                               const float* __restrict__ p2) {
    int row = blockIdx.x;
    int t = threadIdx.x;

    float v1 = p1[row * DIM + t];
    float v2 = p2[row * DIM + t];

    float s1 = v1 * v1, s2 = v2 * v2, s3 = v1 * v2;
    #pragma unroll
    for (int o = 16; o > 0; o >>= 1) {
        s1 += __shfl_down_sync(0xffffffffu, s1, o);
        s2 += __shfl_down_sync(0xffffffffu, s2, o);
        s3 += __shfl_down_sync(0xffffffffu, s3, o);
    }
    __shared__ float sh1[8], sh2[8], sh3[8], shm[8];
    __shared__ float rn1, rn2;
    int wid = t >> 5;
    if ((t & 31) == 0) { sh1[wid] = s1; sh2[wid] = s2; sh3[wid] = s3; }
    __syncthreads();
    if (t == 0) {
        float a = 0.f, b = 0.f, c = 0.f;
        #pragma unroll
        for (int i = 0; i < 8; i++) { a += sh1[i]; b += sh2[i]; c += sh3[i]; }
        float n1 = fmaxf(sqrtf(a), 1e-12f);
        float n2 = fmaxf(sqrtf(b), 1e-12f);
        rn1 = n1; rn2 = n2;
        g_n1[row] = n1;
        g_n2[row] = n2;
        g_diag[row] = c / (n1 * n2);
    }
    __syncthreads();
    float mx = fmaxf(fabsf(v1) / rn1, fabsf(v2) / rn2);
    #pragma unroll
    for (int o = 16; o > 0; o >>= 1)
        mx = fmaxf(mx, __shfl_down_sync(0xffffffffu, mx, o));
    if ((t & 31) == 0) shm[wid] = mx;
    __syncthreads();
    if (t == 0) {
        float m = shm[0];
        #pragma unroll
        for (int i = 1; i < 8; i++) m = fmaxf(m, shm[i]);
        atomicMax(&g_absmax_bits, __float_as_uint(m));   // positive floats: bit-monotone
    }
}

// pass 2: quantize both tensors to int8 with the exact global scale
__global__ void cl_quant_kernel(const float* __restrict__ p1,
                                const float* __restrict__ p2) {
    int g = blockIdx.x * 256 + threadIdx.x;
    int row = g >> 6;
    float S = __uint_as_float(g_absmax_bits);
    float q = 127.0f / S;
    float q1 = q / g_n1[row];
    float q2 = q / g_n2[row];

    float4 a = ((const float4*)p1)[g];
    float4 b = ((const float4*)p2)[g];

    int a0 = __float2int_rn(a.x * q1), a1 = __float2int_rn(a.y * q1);
    int a2 = __float2int_rn(a.z * q1), a3 = __float2int_rn(a.w * q1);
    int b0 = __float2int_rn(b.x * q2), b1 = __float2int_rn(b.y * q2);
    int b2 = __float2int_rn(b.z * q2), b3 = __float2int_rn(b.w * q2);

    g_zi8[g] = (a0 & 0xff) | ((a1 & 0xff) << 8) | ((a2 & 0xff) << 16) | (a3 << 24);
    g_zj8[g] = (b0 & 0xff) | ((b1 & 0xff) << 8) | ((b2 & 0xff) << 16) | (b3 << 24);
}

// fused int8 IMMA GEMM + online LSE, software-pipelined epilogue.
// grid = 128 (64 row-blocks x 2 col-halves); 16 warps as 4x4 -> warp tile 32x32
__global__ void __launch_bounds__(THREADS, 1)
cl_main_kernel() {
    extern __shared__ char smem[];
    uint32_t sb = smem_u32(smem);
    const int tid  = threadIdx.x;
    const int warp = tid >> 5;
    const int lane = tid & 31;
    const int warp_m = warp >> 2;       // 0..3 : 32 rows
    const int warp_n = warp & 3;        // 0..3 : 32 cols
    const int rb   = (blockIdx.x >> 1) * BM;
    const int ch   = blockIdx.x & 1;
    const int col0 = ch * COLSPER;

    const float S = __uint_as_float(g_absmax_bits);
    const float kk = SCALE_L2 * (S * S) * (1.0f / 16129.0f);

    // prologue
    load_tile(sb + SA,  g_zi8 + (size_t)rb * (DIM / 4), tid);
    load_tile(sb + SB0, g_zj8 + (size_t)col0 * (DIM / 4), tid);
    cp_commit();
    load_tile(sb + SB1, g_zj8 + (size_t)(col0 + BN) * (DIM / 4), tid);
    cp_commit();
    cp_wait<1>();
    __syncthreads();

    float m_run[4], s_run[4];
    #pragma unroll
    for (int i = 0; i < 4; i++) { m_run[i] = -1.0e9f; s_run[i] = 0.0f; }

    int accA[2][4][4], accB[2][4][4];

    for (int t = 0; t < TILES; ++t) {
        const uint32_t bbase = sb + ((t & 1) ? SB1 : SB0);
        if (t == 0)
            do_tile<false>(sb, bbase, warp_m, warp_n, lane, accA, accB, m_run, s_run, kk);
        else if (t & 1)
            do_tile<true>(sb, bbase, warp_m, warp_n, lane, accB, accA, m_run, s_run, kk);
        else
            do_tile<true>(sb, bbase, warp_m, warp_n, lane, accA, accB, m_run, s_run, kk);

        __syncthreads();   // all warps done reading B[t&1]
        if (t + 2 < TILES) {
            load_tile(bbase, g_zj8 + (size_t)(col0 + (t + 2) * BN) * (DIM / 4), tid);
            cp_commit();
            cp_wait<1>();  // B[t+1] complete
        } else {
            cp_wait<0>();
        }
        __syncthreads();
    }

    // drain: epilogue of the last tile (TILES-1 is odd -> accB)
    #pragma unroll
    for (int slot = 0; slot < 4; slot++)
        epi_slot(accB, slot, m_run, s_run, kk);

    // ---- reduce across lanes sharing a row (lane&3 varies) ----
    #pragma unroll
    for (int idx = 0; idx < 4; idx++) {
        #pragma unroll
        for (int o = 1; o <= 2; o <<= 1) {
            float om = __shfl_xor_sync(0xffffffffu, m_run[idx], o);
            float os = __shfl_xor_sync(0xffffffffu, s_run[idx], o);
            float nm = fmaxf(m_run[idx], om);
            s_run[idx] = s_run[idx] * ex2f((m_run[idx] - nm) * kk)
                       + os         * ex2f((om         - nm) * kk);
            m_run[idx] = nm;
        }
    }

    // ---- merge across the 4 column-warps via smem ----
    float* mrg_m = (float*)(smem + SMRG_M);
    float* mrg_s = (float*)(smem + SMRG_S);
    if ((lane & 3) == 0) {
        #pragma unroll
        for (int idx = 0; idx < 4; idx++) {
            int row = warp_m * 32 + (idx >> 1) * 16 + (idx & 1) * 8 + (lane >> 2);
            mrg_m[row * 4 + warp_n] = m_run[idx];
            mrg_s[row * 4 + warp_n] = s_run[idx];
        }
    }
    __syncthreads();

    if (tid < BM) {
        int row = tid;
        float m = mrg_m[row * 4];
        #pragma unroll
        for (int w = 1; w < 4; w++) m = fmaxf(m, mrg_m[row * 4 + w]);
        float s = 0.0f;
        #pragma unroll
        for (int w = 0; w < 4; w++)
            s += mrg_s[row * 4 + w] * ex2f((mrg_m[row * 4 + w] - m) * kk);
        g_pm[ch][rb + row] = m;
        g_ps[ch][rb + row] = s;
    }
}

// merge the column-half partials per row, reduce loss + diag, last block writes out
__global__ void cl_merge_kernel(float* out, int out_size) {
    int r = blockIdx.x * 256 + threadIdx.x;
    float S = __uint_as_float(g_absmax_bits);
    float kk = SCALE_L2 * (S * S) * (1.0f / 16129.0f);

    float m = g_pm[0][r];
    #pragma unroll
    for (int c = 1; c < NCH; c++) m = fmaxf(m, g_pm[c][r]);
    float s = 0.0f;
    #pragma unroll
    for (int c = 0; c < NCH; c++)
        s += g_ps[c][r] * ex2f((g_pm[c][r] - m) * kk);

    float d = g_diag[r];
    float loss = LN2F * fmaf(m, kk, log2f(s)) - 1000.0f * d;
    float ds = d;
    #pragma unroll
    for (int o = 16; o; o >>= 1) {
        loss += __shfl_down_sync(0xffffffffu, loss, o);
        ds   += __shfl_down_sync(0xffffffffu, ds, o);
    }
    __shared__ float sl[8], sd[8];
    if ((threadIdx.x & 31) == 0) { sl[threadIdx.x >> 5] = loss; sd[threadIdx.x >> 5] = ds; }
    __syncthreads();
    if (threadIdx.x == 0) {
        float L = 0.f, D = 0.f;
        #pragma unroll
        for (int i = 0; i < 8; i++) { L += sl[i]; D += sd[i]; }
        atomicAdd(&g_loss_sum, L);
        atomicAdd(&g_diag_sum, D);
        __threadfence();
        unsigned int ticket = atomicAdd(&g_done, 1u);
        if (ticket == gridDim.x - 1) {      // last block: sums complete
            if (out_size > 0) out[0] = *(volatile float*)&g_loss_sum / (float)BATCH;
            if (out_size > 1) out[1] = *(volatile float*)&g_diag_sum;
        }
    }
}

// ================= launch =================
extern "C" void kernel_launch(void* const* d_in, const int* in_sizes, int n_in,
                              void* d_out, int out_size) {
    const float* p1 = (const float*)d_in[0];
    const float* p2 = (const float*)d_in[1];
    float* out = (float*)d_out;

    cudaFuncSetAttribute(cl_main_kernel,
                         cudaFuncAttributeMaxDynamicSharedMemorySize, SMEM_BYTES);

    cl_init_kernel<<<1, 1>>>();
    cl_prep_kernel<<<BATCH, DIM>>>(p1, p2);
    cl_quant_kernel<<<BATCH * DIM / 4 / 256, 256>>>(p1, p2);
    cl_main_kernel<<<BATCH / BM * NCH, THREADS, SMEM_BYTES>>>();
    cl_merge_kernel<<<BATCH / 256, 256>>>(out, out_size);
}